// round 1
// baseline (speedup 1.0000x reference)
#include <cuda_runtime.h>

// Problem constants
#define S_   4
#define N_   32768
#define H_   100
#define K_   256
#define MT   64          // n-points per stage-A block
#define PSTR 257         // prec smem row stride (bank-conflict pad)

// shared memory layout for stage A (floats):
//   h1T [100][64] | h2T [100][64] | Wt [100][128] | prS [64][257] | uS [2][64]
#define SM_FLOATS (H_*MT + H_*MT + H_*128 + MT*PSTR + 2*MT)
#define SM_BYTES  (SM_FLOATS * 4)

// Scratch (sanctioned __device__ globals): per-(s,k) reduction accumulators and w.
__device__ float g_acc[S_ * K_ * 5];   // a, b, c, d, e
__device__ float g_w[S_ * K_ * 2];

// ---------------- packed f32x2 helpers (sm_100+) ----------------
static __device__ __forceinline__ unsigned long long pack2(float x, float y) {
    unsigned long long r;
    asm("mov.b64 %0, {%1, %2};" : "=l"(r) : "f"(x), "f"(y));
    return r;
}
static __device__ __forceinline__ void unpack2(unsigned long long p, float &x, float &y) {
    asm("mov.b64 {%0, %1}, %2;" : "=f"(x), "=f"(y) : "l"(p));
}
static __device__ __forceinline__ void ffma2(unsigned long long &d,
                                             unsigned long long a,
                                             unsigned long long b) {
    asm("fma.rn.f32x2 %0, %1, %2, %0;" : "+l"(d) : "l"(a), "l"(b));
}

// ---------------- zero the accumulators (runs first every replay) ----------------
__global__ void zero_acc_kernel() {
    int i = blockIdx.x * 256 + threadIdx.x;
    if (i < S_ * K_ * 5) g_acc[i] = 0.f;
}

// ---------------- Stage A: fused MLP + per-k reductions ----------------
// Block: 256 threads = 16 (tn, rows of 4 n) x 16 (tj, cols of 8).
// Tile: 64 n-points x 128 output columns per GEMM pass.
__global__ void __launch_bounds__(256, 1)
stageA_kernel(const float* __restrict__ U,  const float* __restrict__ W1,
              const float* __restrict__ b1, const float* __restrict__ W2,
              const float* __restrict__ b2, const float* __restrict__ W3,
              const float* __restrict__ b3)
{
    extern __shared__ float sm[];
    float* h1T = sm;                    // [100][64]  (transposed: [i][n])
    float* h2T = h1T + H_ * MT;         // [100][64]
    float* Wt  = h2T + H_ * MT;         // [100][128] staged weights (W2 padded / W3 tiles)
    float* prS = Wt + H_ * 128;         // [64][257]  prec tile
    float* uS  = prS + MT * PSTR;       // [2][64]

    const int tid  = threadIdx.x;
    const int tn   = tid & 15;
    const int tj   = tid >> 4;
    const int s    = blockIdx.y;
    const int n0   = blockIdx.x * MT;
    const int nloc = tn * 4;

    // Load U tile (u0/u1 per point)
    if (tid < MT) {
        const float* up = U + ((size_t)(s * N_ + n0 + tid) << 1);
        uS[tid]      = up[0];
        uS[MT + tid] = up[1];
    }
    // Stage W2 into Wt, zero-padding columns 100..127
    for (int idx = tid; idx < H_ * 128; idx += 256) {
        int i = idx >> 7, j = idx & 127;
        Wt[idx] = (j < H_) ? W2[i * H_ + j] : 0.f;
    }
    __syncthreads();

    // Layer 1: h1T[i][n] = relu(u0*W1[0,i] + u1*W1[1,i] + b1[i])
    for (int idx = tid; idx < H_ * MT; idx += 256) {
        int i = idx >> 6, n = idx & 63;
        float v = fmaf(uS[n], W1[i], fmaf(uS[MT + n], W1[H_ + i], b1[i]));
        h1T[idx] = fmaxf(v, 0.f);
    }
    __syncthreads();

    // ---- GEMM2: h2 = relu(h1 @ W2 + b2), 64x128 tile (cols>=100 are zero) ----
    unsigned long long acc[4][4];
    #pragma unroll
    for (int r = 0; r < 4; ++r)
        #pragma unroll
        for (int c = 0; c < 4; ++c) acc[r][c] = 0ULL;

    #pragma unroll 2
    for (int i = 0; i < H_; ++i) {
        float4 av = *reinterpret_cast<const float4*>(h1T + i * MT + nloc);
        ulonglong2 b01 = *reinterpret_cast<const ulonglong2*>(Wt + i * 128 + tj * 8);
        ulonglong2 b23 = *reinterpret_cast<const ulonglong2*>(Wt + i * 128 + tj * 8 + 4);
        unsigned long long aa[4];
        aa[0] = pack2(av.x, av.x); aa[1] = pack2(av.y, av.y);
        aa[2] = pack2(av.z, av.z); aa[3] = pack2(av.w, av.w);
        unsigned long long bb[4] = { b01.x, b01.y, b23.x, b23.y };
        #pragma unroll
        for (int r = 0; r < 4; ++r)
            #pragma unroll
            for (int c = 0; c < 4; ++c) ffma2(acc[r][c], aa[r], bb[c]);
    }

    // epilogue: +b2, relu, store transposed into h2T (only j < 100)
    #pragma unroll
    for (int c2 = 0; c2 < 4; ++c2) {
        int j0 = tj * 8 + c2 * 2;
        float bj0 = (j0     < H_) ? b2[j0]     : 0.f;
        float bj1 = (j0 + 1 < H_) ? b2[j0 + 1] : 0.f;
        #pragma unroll
        for (int r = 0; r < 4; ++r) {
            float v0, v1; unpack2(acc[r][c2], v0, v1);
            if (j0     < H_) h2T[j0       * MT + nloc + r] = fmaxf(v0 + bj0, 0.f);
            if (j0 + 1 < H_) h2T[(j0 + 1) * MT + nloc + r] = fmaxf(v1 + bj1, 0.f);
        }
    }

    float u0r[4], u1r[4];
    #pragma unroll
    for (int r = 0; r < 4; ++r) { u0r[r] = uS[nloc + r]; u1r[r] = uS[MT + nloc + r]; }

    // ---- GEMM3: aux = h2 @ W3 + b3, four 128-col tiles, fused reductions ----
    for (int jt = 0; jt < 4; ++jt) {
        __syncthreads();   // all reads of Wt (and prev prS writes) done
        for (int idx = tid; idx < H_ * 128; idx += 256) {
            int i = idx >> 7, j = idx & 127;
            Wt[idx] = W3[i * 512 + jt * 128 + j];
        }
        __syncthreads();

        #pragma unroll
        for (int r = 0; r < 4; ++r)
            #pragma unroll
            for (int c = 0; c < 4; ++c) acc[r][c] = 0ULL;

        #pragma unroll 2
        for (int i = 0; i < H_; ++i) {
            float4 av = *reinterpret_cast<const float4*>(h2T + i * MT + nloc);
            ulonglong2 b01 = *reinterpret_cast<const ulonglong2*>(Wt + i * 128 + tj * 8);
            ulonglong2 b23 = *reinterpret_cast<const ulonglong2*>(Wt + i * 128 + tj * 8 + 4);
            unsigned long long aa[4];
            aa[0] = pack2(av.x, av.x); aa[1] = pack2(av.y, av.y);
            aa[2] = pack2(av.z, av.z); aa[3] = pack2(av.w, av.w);
            unsigned long long bb[4] = { b01.x, b01.y, b23.x, b23.y };
            #pragma unroll
            for (int r = 0; r < 4; ++r)
                #pragma unroll
                for (int c = 0; c < 4; ++c) ffma2(acc[r][c], aa[r], bb[c]);
        }

        float b3v[8];
        #pragma unroll
        for (int c = 0; c < 8; ++c) b3v[c] = b3[jt * 128 + tj * 8 + c];

        if (jt < 2) {
            // logprec tiles: prec = exp(aux); accumulate a,b,c; stash prec for mu tiles
            float pa[8], pb[8], pc[8];
            #pragma unroll
            for (int c = 0; c < 8; ++c) { pa[c] = 0.f; pb[c] = 0.f; pc[c] = 0.f; }
            #pragma unroll
            for (int r = 0; r < 4; ++r) {
                float uu00 = u0r[r] * u0r[r];
                float uu01 = u0r[r] * u1r[r];
                float uu11 = u1r[r] * u1r[r];
                float* prow = prS + (nloc + r) * PSTR + jt * 128 + tj * 8;
                #pragma unroll
                for (int c2 = 0; c2 < 4; ++c2) {
                    float v0, v1; unpack2(acc[r][c2], v0, v1);
                    int c = c2 * 2;
                    float p0 = __expf(v0 + b3v[c]);
                    float p1 = __expf(v1 + b3v[c + 1]);
                    prow[c] = p0; prow[c + 1] = p1;
                    pa[c]     += p0 * uu00; pb[c]     += p0 * uu01; pc[c]     += p0 * uu11;
                    pa[c + 1] += p1 * uu00; pb[c + 1] += p1 * uu01; pc[c + 1] += p1 * uu11;
                }
            }
            #pragma unroll
            for (int c = 0; c < 8; ++c)
                #pragma unroll
                for (int off = 8; off; off >>= 1) {
                    pa[c] += __shfl_xor_sync(0xffffffffu, pa[c], off);
                    pb[c] += __shfl_xor_sync(0xffffffffu, pb[c], off);
                    pc[c] += __shfl_xor_sync(0xffffffffu, pc[c], off);
                }
            if (tn == 0) {
                int kb = jt * 128 + tj * 8;
                #pragma unroll
                for (int c = 0; c < 8; ++c) {
                    float* gp = g_acc + ((s * K_) + kb + c) * 5;
                    atomicAdd(gp,     pa[c]);
                    atomicAdd(gp + 1, pb[c]);
                    atomicAdd(gp + 2, pc[c]);
                }
            }
        } else {
            // mu tiles: pm = prec*mu; accumulate d,e
            float pd[8], pe[8];
            #pragma unroll
            for (int c = 0; c < 8; ++c) { pd[c] = 0.f; pe[c] = 0.f; }
            #pragma unroll
            for (int r = 0; r < 4; ++r) {
                const float* prow = prS + (nloc + r) * PSTR + (jt - 2) * 128 + tj * 8;
                #pragma unroll
                for (int c2 = 0; c2 < 4; ++c2) {
                    float v0, v1; unpack2(acc[r][c2], v0, v1);
                    int c = c2 * 2;
                    float pm0 = prow[c]     * (v0 + b3v[c]);
                    float pm1 = prow[c + 1] * (v1 + b3v[c + 1]);
                    pd[c]     += pm0 * u0r[r]; pe[c]     += pm0 * u1r[r];
                    pd[c + 1] += pm1 * u0r[r]; pe[c + 1] += pm1 * u1r[r];
                }
            }
            #pragma unroll
            for (int c = 0; c < 8; ++c)
                #pragma unroll
                for (int off = 8; off; off >>= 1) {
                    pd[c] += __shfl_xor_sync(0xffffffffu, pd[c], off);
                    pe[c] += __shfl_xor_sync(0xffffffffu, pe[c], off);
                }
            if (tn == 0) {
                int kb = (jt - 2) * 128 + tj * 8;
                #pragma unroll
                for (int c = 0; c < 8; ++c) {
                    float* gp = g_acc + ((s * K_) + kb + c) * 5;
                    atomicAdd(gp + 3, pd[c]);
                    atomicAdd(gp + 4, pe[c]);
                }
            }
        }
    }
}

// ---------------- Stage B: per-(s,k) 2x2 posterior + KL ----------------
__global__ void stageB_kernel(const float* __restrict__ eps, float* __restrict__ kl_out)
{
    __shared__ float red[256];
    const int s = blockIdx.x;
    const int k = threadIdx.x;
    const float* a = g_acc + (s * K_ + k) * 5;

    float A = a[0] + 1.f;     // q_prec = UTLU + I (PRIOR_VAR = 1)
    float B = a[1];
    float C = a[2] + 1.f;
    float dd = a[3], ee = a[4];

    float det = A * C - B * B;
    float inv = 1.f / det;
    float c00 = C * inv, c01 = -B * inv, c11 = A * inv;   // q_cov
    float qm0 = c00 * dd + c01 * ee;                      // q_mu
    float qm1 = c01 * dd + c11 * ee;

    float l00 = sqrtf(c00);                               // Lc = chol(q_cov)
    float l10 = c01 / l00;
    float l11 = sqrtf(fmaxf(c11 - l10 * l10, 0.f));

    float e0 = eps[(s * K_ + k) * 2];
    float e1 = eps[(s * K_ + k) * 2 + 1];
    g_w[(s * K_ + k) * 2]     = qm0 + l00 * e0;
    g_w[(s * K_ + k) * 2 + 1] = qm1 + l10 * e0 + l11 * e1;

    // kl_k = 0.5*(tr_cov + |q_mu|^2 - D + log det(q_prec))
    float kl = 0.5f * ((c00 + c11) + (qm0 * qm0 + qm1 * qm1) - 2.f + logf(det));
    red[k] = kl;
    __syncthreads();
    for (int off = 128; off; off >>= 1) {
        if (k < off) red[k] += red[k + off];
        __syncthreads();
    }
    if (k == 0) kl_out[s] = red[0];
}

// ---------------- Stage C: out_U = relu(U . w), bandwidth bound ----------------
__global__ void __launch_bounds__(256)
stageC_kernel(const float* __restrict__ U, float* __restrict__ out)
{
    __shared__ float w0s[K_], w1s[K_], u0s[64], u1s[64];
    const int s  = blockIdx.y;
    const int n0 = blockIdx.x * 64;
    const int tid = threadIdx.x;

    w0s[tid] = g_w[(s * K_ + tid) * 2];
    w1s[tid] = g_w[(s * K_ + tid) * 2 + 1];
    if (tid < 64) {
        const float* up = U + ((size_t)(s * N_ + n0 + tid) << 1);
        u0s[tid] = up[0];
        u1s[tid] = up[1];
    }
    __syncthreads();

    const int kq = tid & 63;   // float4 column group
    const int r  = tid >> 6;   // row within group of 4
    #pragma unroll
    for (int nn = 0; nn < 16; ++nn) {
        int nl = nn * 4 + r;
        float u0 = u0s[nl], u1 = u1s[nl];
        int k = kq * 4;
        float4 o;
        o.x = fmaxf(fmaf(u0, w0s[k],     u1 * w1s[k]),     0.f);
        o.y = fmaxf(fmaf(u0, w0s[k + 1], u1 * w1s[k + 1]), 0.f);
        o.z = fmaxf(fmaf(u0, w0s[k + 2], u1 * w1s[k + 2]), 0.f);
        o.w = fmaxf(fmaf(u0, w0s[k + 3], u1 * w1s[k + 3]), 0.f);
        reinterpret_cast<float4*>(out)[(((size_t)(s * N_ + n0 + nl)) * K_ + k) >> 2] = o;
    }
}

// ---------------- launch ----------------
extern "C" void kernel_launch(void* const* d_in, const int* in_sizes, int n_in,
                              void* d_out, int out_size)
{
    const float* U   = (const float*)d_in[0];
    const float* eps = (const float*)d_in[1];
    const float* W1  = (const float*)d_in[2];
    const float* b1  = (const float*)d_in[3];
    const float* W2  = (const float*)d_in[4];
    const float* b2  = (const float*)d_in[5];
    const float* W3  = (const float*)d_in[6];
    const float* b3  = (const float*)d_in[7];
    float* out = (float*)d_out;

    cudaFuncSetAttribute((const void*)stageA_kernel,
                         cudaFuncAttributeMaxDynamicSharedMemorySize, SM_BYTES);

    zero_acc_kernel<<<(S_ * K_ * 5 + 255) / 256, 256>>>();
    stageA_kernel<<<dim3(N_ / MT, S_), 256, SM_BYTES>>>(U, W1, b1, W2, b2, W3, b3);
    // kl scalars live in the last S_ floats of the output buffer
    stageB_kernel<<<S_, 256>>>(eps, out + (out_size - S_));
    stageC_kernel<<<dim3(N_ / 64, S_), 256>>>(U, out);
}

// round 3
// speedup vs baseline: 1.6676x; 1.6676x over previous
#include <cuda_runtime.h>

// Problem constants
#define S_   4
#define N_   32768
#define H_   100
#define K_   256
#define MT   64          // n-points per stage-A block
#define CH   25          // k-rows per weight chunk
#define NCH  4           // 100 / 25

// stage-A shared memory (floats):
//   h1T[100][64] | h2T[100][64] | Wt[2][25*256] | uS[2][64]
#define SM_FLOATS (H_*MT + H_*MT + 2*CH*256 + 2*MT)
#define SM_BYTES  (SM_FLOATS * 4)

// Scratch (__device__ globals): per-(s,k) accumulators and w.
__device__ float g_acc[S_ * K_ * 5];   // a, b, c, d, e
__device__ float g_w[S_ * K_ * 2];

// ---------------- packed f32x2 helpers (sm_100+) ----------------
static __device__ __forceinline__ unsigned long long pack2(float x, float y) {
    unsigned long long r;
    asm("mov.b64 %0, {%1, %2};" : "=l"(r) : "f"(x), "f"(y));
    return r;
}
static __device__ __forceinline__ void unpack2(unsigned long long p, float &x, float &y) {
    asm("mov.b64 {%0, %1}, %2;" : "=f"(x), "=f"(y) : "l"(p));
}
static __device__ __forceinline__ void ffma2(unsigned long long &d,
                                             unsigned long long a,
                                             unsigned long long b) {
    asm("fma.rn.f32x2 %0, %1, %2, %0;" : "+l"(d) : "l"(a), "l"(b));
}

// ---------------- cp.async helpers ----------------
static __device__ __forceinline__ unsigned smem_u32(const void* p) {
    return (unsigned)__cvta_generic_to_shared(p);
}
static __device__ __forceinline__ void cpa16(unsigned dst, const float* src) {
    asm volatile("cp.async.cg.shared.global [%0], [%1], 16;\n" :: "r"(dst), "l"(src));
}
#define CPA_COMMIT() asm volatile("cp.async.commit_group;\n" ::: "memory")
#define CPA_WAIT0()  asm volatile("cp.async.wait_group 0;\n" ::: "memory")

// ---------------- zero the accumulators (runs first every replay) ----------------
__global__ void zero_acc_kernel() {
    int i = blockIdx.x * 256 + threadIdx.x;
    if (i < S_ * K_ * 5) g_acc[i] = 0.f;
}

// ---------------- Stage A ----------------
// 256 threads = 16 (tn: 4 rows each) x 16 (tj: 8 cols each).
// GEMM2: 64x128 tile. GEMM3: two passes, each 64 x (128 logprec + 128 mu),
// pairing column k with k+256 so prec never leaves registers.
__global__ void __launch_bounds__(256, 2)
stageA_kernel(const float* __restrict__ U,  const float* __restrict__ W1,
              const float* __restrict__ b1, const float* __restrict__ W2,
              const float* __restrict__ b2, const float* __restrict__ W3,
              const float* __restrict__ b3)
{
    extern __shared__ float sm[];
    float* h1T = sm;                     // [100][64]
    float* h2T = h1T + H_ * MT;          // [100][64]
    float* Wt  = h2T + H_ * MT;          // [2][25*256]
    float* uS  = Wt + 2 * CH * 256;      // [2][64]

    const int tid  = threadIdx.x;
    const int tn   = tid & 15;
    const int tj   = tid >> 4;
    const int s    = blockIdx.y;
    const int n0   = blockIdx.x * MT;
    const int nloc = tn * 4;

    // Load U tile; kick off W2 chunk 0 staging immediately (independent).
    if (tid < MT) {
        const float* up = U + ((size_t)(s * N_ + n0 + tid) << 1);
        uS[tid]      = up[0];
        uS[MT + tid] = up[1];
    }
    {
        float* dst = Wt;  // buffer 0, GEMM2 row stride 128
        for (int idx = tid; idx < CH * 32; idx += 256) {
            int row = idx >> 5, c = (idx & 31) * 4;
            if (c < H_) cpa16(smem_u32(dst + row * 128 + c), W2 + row * H_ + c);
            else *reinterpret_cast<float4*>(dst + row * 128 + c) = make_float4(0.f, 0.f, 0.f, 0.f);
        }
        CPA_COMMIT();
    }
    __syncthreads();

    // Layer 1: h1T[i][n] = relu(u0*W1[0,i] + u1*W1[1,i] + b1[i])
    for (int idx = tid; idx < H_ * MT; idx += 256) {
        int i = idx >> 6, n = idx & 63;
        float v = fmaf(uS[n], W1[i], fmaf(uS[MT + n], W1[H_ + i], b1[i]));
        h1T[idx] = fmaxf(v, 0.f);
    }

    // ---- GEMM2: h2 = relu(h1 @ W2 + b2), chunked + double buffered ----
    unsigned long long acc2[4][4];
    #pragma unroll
    for (int r = 0; r < 4; ++r)
        #pragma unroll
        for (int c = 0; c < 4; ++c) acc2[r][c] = 0ULL;

    int cb = 0;
    for (int ch = 0; ch < NCH; ++ch) {
        CPA_WAIT0();
        __syncthreads();                 // chunk data visible; h1T/compute(ch-1) done
        if (ch + 1 < NCH) {
            float* dst = Wt + (cb ^ 1) * CH * 256;
            for (int idx = tid; idx < CH * 32; idx += 256) {
                int row = idx >> 5, c = (idx & 31) * 4;
                if (c < H_) cpa16(smem_u32(dst + row * 128 + c),
                                  W2 + (size_t)((ch + 1) * CH + row) * H_ + c);
                else *reinterpret_cast<float4*>(dst + row * 128 + c) = make_float4(0.f, 0.f, 0.f, 0.f);
            }
            CPA_COMMIT();
        }
        const float* buf = Wt + cb * CH * 256;
        #pragma unroll 5
        for (int i = 0; i < CH; ++i) {
            float4 av = *reinterpret_cast<const float4*>(h1T + (ch * CH + i) * MT + nloc);
            const float* bp = buf + i * 128 + tj * 8;
            ulonglong2 b01 = *reinterpret_cast<const ulonglong2*>(bp);
            ulonglong2 b23 = *reinterpret_cast<const ulonglong2*>(bp + 4);
            unsigned long long aa[4];
            aa[0] = pack2(av.x, av.x); aa[1] = pack2(av.y, av.y);
            aa[2] = pack2(av.z, av.z); aa[3] = pack2(av.w, av.w);
            unsigned long long bb[4] = { b01.x, b01.y, b23.x, b23.y };
            #pragma unroll
            for (int r = 0; r < 4; ++r)
                #pragma unroll
                for (int c = 0; c < 4; ++c) ffma2(acc2[r][c], aa[r], bb[c]);
        }
        cb ^= 1;
    }

    // GEMM2 epilogue: +b2, relu, store transposed into h2T (only j < 100)
    #pragma unroll
    for (int c2 = 0; c2 < 4; ++c2) {
        int j0 = tj * 8 + c2 * 2;
        float bj0 = (j0     < H_) ? b2[j0]     : 0.f;
        float bj1 = (j0 + 1 < H_) ? b2[j0 + 1] : 0.f;
        #pragma unroll
        for (int r = 0; r < 4; ++r) {
            float v0, v1; unpack2(acc2[r][c2], v0, v1);
            if (j0     < H_) h2T[j0       * MT + nloc + r] = fmaxf(v0 + bj0, 0.f);
            if (j0 + 1 < H_) h2T[(j0 + 1) * MT + nloc + r] = fmaxf(v1 + bj1, 0.f);
        }
    }

    // ---- GEMM3: two passes; each computes logprec cols [kb,kb+128) AND
    //      mu cols [256+kb, 256+kb+128) together, fusing the reductions. ----
    for (int p = 0; p < 2; ++p) {
        const int kb = p * 128;
        // stage chunk 0 of this pass into buffer cb (row stride 256: 64 float4/row)
        {
            float* dst = Wt + cb * CH * 256;
            for (int idx = tid; idx < CH * 64; idx += 256) {
                int row = idx >> 6, c = (idx & 63) * 4;
                int col = (c < 128) ? (kb + c) : (256 + kb + (c - 128));
                cpa16(smem_u32(dst + row * 256 + c), W3 + (size_t)row * 512 + col);
            }
            CPA_COMMIT();
        }

        unsigned long long aLP[4][4], aMU[4][4];
        #pragma unroll
        for (int r = 0; r < 4; ++r)
            #pragma unroll
            for (int c = 0; c < 4; ++c) { aLP[r][c] = 0ULL; aMU[r][c] = 0ULL; }

        for (int ch = 0; ch < NCH; ++ch) {
            CPA_WAIT0();
            __syncthreads();
            if (ch + 1 < NCH) {
                float* dst = Wt + (cb ^ 1) * CH * 256;
                for (int idx = tid; idx < CH * 64; idx += 256) {
                    int row = idx >> 6, c = (idx & 63) * 4;
                    int col = (c < 128) ? (kb + c) : (256 + kb + (c - 128));
                    cpa16(smem_u32(dst + row * 256 + c),
                          W3 + (size_t)((ch + 1) * CH + row) * 512 + col);
                }
                CPA_COMMIT();
            }
            const float* buf = Wt + cb * CH * 256;
            #pragma unroll 5
            for (int i = 0; i < CH; ++i) {
                float4 av = *reinterpret_cast<const float4*>(h2T + (ch * CH + i) * MT + nloc);
                const float* bl = buf + i * 256 + tj * 8;
                ulonglong2 l01 = *reinterpret_cast<const ulonglong2*>(bl);
                ulonglong2 l23 = *reinterpret_cast<const ulonglong2*>(bl + 4);
                ulonglong2 m01 = *reinterpret_cast<const ulonglong2*>(bl + 128);
                ulonglong2 m23 = *reinterpret_cast<const ulonglong2*>(bl + 132);
                unsigned long long aa[4];
                aa[0] = pack2(av.x, av.x); aa[1] = pack2(av.y, av.y);
                aa[2] = pack2(av.z, av.z); aa[3] = pack2(av.w, av.w);
                unsigned long long bL[4] = { l01.x, l01.y, l23.x, l23.y };
                unsigned long long bM[4] = { m01.x, m01.y, m23.x, m23.y };
                #pragma unroll
                for (int r = 0; r < 4; ++r) {
                    #pragma unroll
                    for (int c = 0; c < 4; ++c) ffma2(aLP[r][c], aa[r], bL[c]);
                    #pragma unroll
                    for (int c = 0; c < 4; ++c) ffma2(aMU[r][c], aa[r], bM[c]);
                }
            }
            cb ^= 1;
        }

        // fused epilogue: prec = exp(lp + b3), pm = prec*(mu + b3'), reduce a..e
        float b3l[8], b3m[8];
        #pragma unroll
        for (int c = 0; c < 8; ++c) {
            b3l[c] = b3[kb + tj * 8 + c];
            b3m[c] = b3[256 + kb + tj * 8 + c];
        }
        float pa[8], pb_[8], pc_[8], pd[8], pe[8];
        #pragma unroll
        for (int c = 0; c < 8; ++c) { pa[c]=0.f; pb_[c]=0.f; pc_[c]=0.f; pd[c]=0.f; pe[c]=0.f; }

        #pragma unroll
        for (int r = 0; r < 4; ++r) {
            float u0 = uS[nloc + r], u1 = uS[MT + nloc + r];
            float uu00 = u0 * u0, uu01 = u0 * u1, uu11 = u1 * u1;
            #pragma unroll
            for (int c2 = 0; c2 < 4; ++c2) {
                float l0, l1, m0, m1;
                unpack2(aLP[r][c2], l0, l1);
                unpack2(aMU[r][c2], m0, m1);
                int c = c2 * 2;
                float p0 = __expf(l0 + b3l[c]);
                float p1 = __expf(l1 + b3l[c + 1]);
                float pm0 = p0 * (m0 + b3m[c]);
                float pm1 = p1 * (m1 + b3m[c + 1]);
                pa[c]     += p0 * uu00; pb_[c]     += p0 * uu01; pc_[c]     += p0 * uu11;
                pd[c]     += pm0 * u0;  pe[c]      += pm0 * u1;
                pa[c + 1] += p1 * uu00; pb_[c + 1] += p1 * uu01; pc_[c + 1] += p1 * uu11;
                pd[c + 1] += pm1 * u0;  pe[c + 1]  += pm1 * u1;
            }
        }
        #pragma unroll
        for (int c = 0; c < 8; ++c)
            #pragma unroll
            for (int off = 8; off; off >>= 1) {
                pa[c]  += __shfl_xor_sync(0xffffffffu, pa[c],  off);
                pb_[c] += __shfl_xor_sync(0xffffffffu, pb_[c], off);
                pc_[c] += __shfl_xor_sync(0xffffffffu, pc_[c], off);
                pd[c]  += __shfl_xor_sync(0xffffffffu, pd[c],  off);
                pe[c]  += __shfl_xor_sync(0xffffffffu, pe[c],  off);
            }
        if (tn == 0) {
            int kbase = kb + tj * 8;
            #pragma unroll
            for (int c = 0; c < 8; ++c) {
                float* gp = g_acc + ((s * K_) + kbase + c) * 5;
                atomicAdd(gp,     pa[c]);
                atomicAdd(gp + 1, pb_[c]);
                atomicAdd(gp + 2, pc_[c]);
                atomicAdd(gp + 3, pd[c]);
                atomicAdd(gp + 4, pe[c]);
            }
        }
    }
}

// ---------------- Stage B: per-(s,k) 2x2 posterior + KL ----------------
__global__ void stageB_kernel(const float* __restrict__ eps, float* __restrict__ kl_out)
{
    __shared__ float red[256];
    const int s = blockIdx.x;
    const int k = threadIdx.x;
    const float* a = g_acc + (s * K_ + k) * 5;

    float A = a[0] + 1.f;     // q_prec = UTLU + I (PRIOR_VAR = 1)
    float B = a[1];
    float C = a[2] + 1.f;
    float dd = a[3], ee = a[4];

    float det = A * C - B * B;
    float inv = 1.f / det;
    float c00 = C * inv, c01 = -B * inv, c11 = A * inv;   // q_cov
    float qm0 = c00 * dd + c01 * ee;                      // q_mu
    float qm1 = c01 * dd + c11 * ee;

    float l00 = sqrtf(c00);                               // Lc = chol(q_cov)
    float l10 = c01 / l00;
    float l11 = sqrtf(fmaxf(c11 - l10 * l10, 0.f));

    float e0 = eps[(s * K_ + k) * 2];
    float e1 = eps[(s * K_ + k) * 2 + 1];
    g_w[(s * K_ + k) * 2]     = qm0 + l00 * e0;
    g_w[(s * K_ + k) * 2 + 1] = qm1 + l10 * e0 + l11 * e1;

    float kl = 0.5f * ((c00 + c11) + (qm0 * qm0 + qm1 * qm1) - 2.f + logf(det));
    red[k] = kl;
    __syncthreads();
    for (int off = 128; off; off >>= 1) {
        if (k < off) red[k] += red[k + off];
        __syncthreads();
    }
    if (k == 0) kl_out[s] = red[0];
}

// ---------------- Stage C: out_U = relu(U . w), bandwidth bound ----------------
__global__ void __launch_bounds__(256)
stageC_kernel(const float* __restrict__ U, float* __restrict__ out)
{
    __shared__ float w0s[K_], w1s[K_], u0s[64], u1s[64];
    const int s  = blockIdx.y;
    const int n0 = blockIdx.x * 64;
    const int tid = threadIdx.x;

    w0s[tid] = g_w[(s * K_ + tid) * 2];
    w1s[tid] = g_w[(s * K_ + tid) * 2 + 1];
    if (tid < 64) {
        const float* up = U + ((size_t)(s * N_ + n0 + tid) << 1);
        u0s[tid] = up[0];
        u1s[tid] = up[1];
    }
    __syncthreads();

    const int kq = tid & 63;
    const int r  = tid >> 6;
    #pragma unroll
    for (int nn = 0; nn < 16; ++nn) {
        int nl = nn * 4 + r;
        float u0 = u0s[nl], u1 = u1s[nl];
        int k = kq * 4;
        float4 o;
        o.x = fmaxf(fmaf(u0, w0s[k],     u1 * w1s[k]),     0.f);
        o.y = fmaxf(fmaf(u0, w0s[k + 1], u1 * w1s[k + 1]), 0.f);
        o.z = fmaxf(fmaf(u0, w0s[k + 2], u1 * w1s[k + 2]), 0.f);
        o.w = fmaxf(fmaf(u0, w0s[k + 3], u1 * w1s[k + 3]), 0.f);
        reinterpret_cast<float4*>(out)[(((size_t)(s * N_ + n0 + nl)) * K_ + k) >> 2] = o;
    }
}

// ---------------- launch ----------------
extern "C" void kernel_launch(void* const* d_in, const int* in_sizes, int n_in,
                              void* d_out, int out_size)
{
    const float* U   = (const float*)d_in[0];
    const float* eps = (const float*)d_in[1];
    const float* W1  = (const float*)d_in[2];
    const float* b1  = (const float*)d_in[3];
    const float* W2  = (const float*)d_in[4];
    const float* b2  = (const float*)d_in[5];
    const float* W3  = (const float*)d_in[6];
    const float* b3  = (const float*)d_in[7];
    float* out = (float*)d_out;

    cudaFuncSetAttribute((const void*)stageA_kernel,
                         cudaFuncAttributeMaxDynamicSharedMemorySize, SM_BYTES);

    zero_acc_kernel<<<(S_ * K_ * 5 + 255) / 256, 256>>>();
    stageA_kernel<<<dim3(N_ / MT, S_), 256, SM_BYTES>>>(U, W1, b1, W2, b2, W3, b3);
    stageB_kernel<<<S_, 256>>>(eps, out + (out_size - S_));
    stageC_kernel<<<dim3(N_ / 64, S_), 256>>>(U, out);
}